// round 6
// baseline (speedup 1.0000x reference)
#include <cuda_runtime.h>
#include <math.h>

#define BATCH 8
#define CCH 96
#define HH 96
#define WW 96
#define HW (HH*WW)                 // 9216
#define NPIX 7077888               // 8*96*96*96
#define N1OUT 14155776             // 8*192*96*96

// weight layout: [chunk][tap(9)][cotile(6)][lane(32)][4 frag words]
#define WCH2  6912                 // words per 8-ci chunk = 9*6*32*4
// patch smem: [ci4(4)][row(10)][col(18) pairs] pair=(ci,ci+4)
#define PRS2  40                   // row stride (words), padded
#define PCIS  400                  // ci4 stride = 10*PRS2
#define PBUF  1600                 // 4*PCIS

// ---------------- scratch (static __device__, no allocation) ----------------
__device__ float g_y1[NPIX];
__device__ float g_y2[NPIX];
__device__ float g_q [NPIX];
__device__ float g_k [NPIX];
__device__ float g_y3[NPIX];
__device__ float g_attn[BATCH*CCH*CCH*9];   // [b][ck][cq][p]
__device__ float g_mean[3*CCH];
__device__ float g_istd[3*CCH];

// tf32 inputs / outputs
__device__ __align__(16) unsigned g_x1t[NPIX];
__device__ __align__(16) unsigned g_x2t[NPIX];
__device__ __align__(16) unsigned g_vt [NPIX];
// fragment-order tf32 weights
__device__ __align__(16) unsigned g_w1t [12*WCH2];
__device__ __align__(16) unsigned g_w2t [12*WCH2];
__device__ __align__(16) unsigned g_wa1t[24*WCH2];
__device__ __align__(16) unsigned g_wa2t[24*WCH2];
__device__ __align__(16) unsigned g_wa3t[24*WCH2];
__device__ __align__(16) unsigned g_wat [BATCH*12*WCH2];

__device__ __forceinline__ unsigned f2tf32(float v) {
    unsigned u;
    asm("cvt.rna.tf32.f32 %0, %1;" : "=r"(u) : "f"(v));
    return u;
}

// ---------------- merged input fp32 -> tf32 ----------------
__global__ __launch_bounds__(256)
void cvt_all_kernel(const float* __restrict__ x1, const float* __restrict__ x2,
                    unsigned* __restrict__ d1, unsigned* __restrict__ d2)
{
    int i = blockIdx.x*256 + threadIdx.x;
    if (i >= NPIX) return;
    if (blockIdx.y == 0) d1[i] = f2tf32(x1[i]);
    else                 d2[i] = f2tf32(x2[i]);
}

// ---------------- merged weight pre-transform (fragment order) -------------
// dst word e: chunk=e/WCH2; rm=e%WCH2; word=rm&3; lane=(rm>>2)&31; mtap=rm>>7;
// tap=mtap/6; mt=mtap%6; g=lane>>2; t=lane&3
// co = mt*16 + g + (word&1)*8 ; ci = chunk*8 + t + ((word>>1)&1)*4
__global__ __launch_bounds__(256)
void wprep_all_kernel(const float* __restrict__ w1, const float* __restrict__ w2,
                      const float* __restrict__ wa1, const float* __restrict__ wa2,
                      const float* __restrict__ wa3,
                      unsigned* __restrict__ d1, unsigned* __restrict__ d2,
                      unsigned* __restrict__ d3, unsigned* __restrict__ d4,
                      unsigned* __restrict__ d5)
{
    const int id = blockIdx.y;
    const float* src; unsigned* dst; int cin;
    if      (id == 0) { src = w1;  dst = d1; cin = 96;  }
    else if (id == 1) { src = w2;  dst = d2; cin = 96;  }
    else if (id == 2) { src = wa1; dst = d3; cin = 192; }
    else if (id == 3) { src = wa2; dst = d4; cin = 192; }
    else              { src = wa3; dst = d5; cin = 192; }
    const int nwords = (cin >> 3) * WCH2;
    int e = blockIdx.x*256 + threadIdx.x;
    if (e >= nwords) return;
    int chunk = e / WCH2, rm = e - chunk*WCH2;
    int word = rm & 3, lane = (rm >> 2) & 31, mtap = rm >> 7;
    int tap = mtap / 6, mt = mtap - 6*tap;
    int g = lane >> 2, t = lane & 3;
    int co = mt*16 + g + (word & 1)*8;
    int ci = chunk*8 + t + ((word >> 1) & 1)*4;
    dst[e] = f2tf32(src[((size_t)co*cin + ci)*9 + tap]);
}

// attn weights -> fragment order, per batch
__global__ __launch_bounds__(256)
void wprep_attn_kernel(const float* __restrict__ attn, unsigned* __restrict__ dst)
{
    const int b = blockIdx.z;
    int e = blockIdx.x*256 + threadIdx.x;
    if (e >= 12*WCH2) return;
    int chunk = e / WCH2, rm = e - chunk*WCH2;
    int word = rm & 3, lane = (rm >> 2) & 31, mtap = rm >> 7;
    int tap = mtap / 6, mt = mtap - 6*tap;
    int g = lane >> 2, t = lane & 3;
    int co = mt*16 + g + (word & 1)*8;
    int ci = chunk*8 + t + ((word >> 1) & 1)*4;
    dst[(size_t)b*12*WCH2 + e] =
        f2tf32(attn[(size_t)b*CCH*CCH*9 + ((size_t)co*CCH + ci)*9 + tap]);
}

// ---------------- tensor-core 3x3 conv, fragment-order operands -------------
// block: 384 thr (12 warps) -> tile 96co x 128px (8 rows x 16 cols)
// warp: cog=wid>>2 (32 co = 2 m-tiles), rp=wid&3 (rows 2rp,2rp+1); 4 n-tiles
__global__ __launch_bounds__(384, 2)
void conv3x3_tc3_kernel(const unsigned* __restrict__ inAt, const unsigned* __restrict__ inBt,
                        int csplit, int cin,
                        const unsigned* __restrict__ wtf, long wbstride,
                        void* __restrict__ outp, int outtf32)
{
    extern __shared__ unsigned dsm[];        // [2*WCH2 weights][2*PBUF patch]
    const int tid  = threadIdx.x;
    const int lane = tid & 31, wid = tid >> 5;
    const int g = lane >> 2, t = lane & 3;
    const int cog = wid >> 2;                // 0..2
    const int rp  = wid & 3;                 // 0..3
    const int b   = blockIdx.z;
    const int byk = blockIdx.x / 6, bxk = blockIdx.x - 6*byk;
    const int by0 = byk*8, bx0 = bxk*16;

    const unsigned smem_b = (unsigned)__cvta_generic_to_shared(dsm);
    unsigned* psmem = dsm + 2*WCH2;

    // ---- hoisted patch geometry (1440 elems = 8ci x 10r x 18c) ----
    int pgoff[4], psoff[4], pci[4];
    bool lok[4], sok[4];
    #pragma unroll
    for (int it = 0; it < 4; it++) {
        int e = tid + it*384;
        int ci = e / 180, r2 = e - ci*180;
        int row = r2 / 18, col = r2 - row*18;
        int gh = by0 + row - 1, gw = bx0 + col - 1;
        bool inp = (e < 1440);
        bool ok = inp && gh >= 0 && gh < HH && gw >= 0 && gw < WW;
        lok[it] = ok; sok[it] = inp;
        pgoff[it] = ok ? gh*WW + gw : 0;
        psoff[it] = inp ? (ci & 3)*PCIS + row*PRS2 + col*2 + (ci >> 2) : 0;
        pci[it]   = ci;
    }

    const unsigned* wsrc0 = wtf + (size_t)wbstride*b;

    // ---- prologue: chunk 0 into buffer 0 ----
    #pragma unroll
    for (int k2 = 0; k2 < 5; k2++) {
        int idx = tid + k2*384;
        if (idx < WCH2/4)
            asm volatile("cp.async.cg.shared.global [%0], [%1], 16;"
                         :: "r"(smem_b + idx*16), "l"(wsrc0 + idx*4) : "memory");
    }
    asm volatile("cp.async.commit_group;" ::: "memory");
    {
        unsigned pv[4];
        #pragma unroll
        for (int it = 0; it < 4; it++) {
            int gci = pci[it];
            const unsigned* src = (gci < csplit)
                ? inAt + ((size_t)b*csplit + gci)*HW
                : inBt + ((size_t)b*(cin-csplit) + (gci-csplit))*HW;
            pv[it] = lok[it] ? src[pgoff[it]] : 0u;
        }
        #pragma unroll
        for (int it = 0; it < 4; it++)
            if (sok[it]) psmem[psoff[it]] = pv[it];
    }
    asm volatile("cp.async.wait_group 0;" ::: "memory");
    __syncthreads();

    float acc[2][4][4];
    #pragma unroll
    for (int m=0;m<2;m++)
        #pragma unroll
        for (int nt=0;nt<4;nt++)
            #pragma unroll
            for (int r=0;r<4;r++) acc[m][nt][r] = 0.f;

    const int nchunk = cin >> 3;
    for (int ch = 0; ch < nchunk; ch++) {
        const int cur = ch & 1;
        const bool more = (ch + 1 < nchunk);

        // stage next chunk
        unsigned pv[4];
        if (more) {
            const unsigned* wsrc = wsrc0 + (size_t)(ch+1)*WCH2;
            const unsigned wdst = smem_b + (cur^1)*WCH2*4;
            #pragma unroll
            for (int k2 = 0; k2 < 5; k2++) {
                int idx = tid + k2*384;
                if (idx < WCH2/4)
                    asm volatile("cp.async.cg.shared.global [%0], [%1], 16;"
                                 :: "r"(wdst + idx*16), "l"(wsrc + idx*4) : "memory");
            }
            asm volatile("cp.async.commit_group;" ::: "memory");
            const int ci0 = (ch+1) << 3;
            #pragma unroll
            for (int it = 0; it < 4; it++) {
                int gci = ci0 + pci[it];
                const unsigned* src = (gci < csplit)
                    ? inAt + ((size_t)b*csplit + gci)*HW
                    : inBt + ((size_t)b*(cin-csplit) + (gci-csplit))*HW;
                pv[it] = lok[it] ? src[pgoff[it]] : 0u;
            }
        }

        // ---- mma on current buffers ----
        const unsigned wbase = smem_b + cur*WCH2*4;
        const unsigned pbase = smem_b + (2*WCH2 + cur*PBUF)*4;
        #pragma unroll
        for (int tap = 0; tap < 9; tap++) {
            const int i = tap/3, j = tap - 3*(tap/3);
            unsigned a[2][4];
            #pragma unroll
            for (int m = 0; m < 2; m++) {
                const int mt = cog*2 + m;
                asm volatile("ld.shared.v4.b32 {%0,%1,%2,%3}, [%4];"
                    : "=r"(a[m][0]), "=r"(a[m][1]), "=r"(a[m][2]), "=r"(a[m][3])
                    : "r"(wbase + (((tap*6 + mt)*32 + lane)*16)));
            }
            #pragma unroll
            for (int nt = 0; nt < 4; nt++) {
                const int py = 2*rp + (nt & 1);
                const int cb2 = (nt >> 1) * 8;
                unsigned b0, b1;
                asm volatile("ld.shared.v2.b32 {%0,%1}, [%2];"
                    : "=r"(b0), "=r"(b1)
                    : "r"(pbase + (t*PCIS + (py+i)*PRS2 + (cb2+j+g)*2)*4));
                #pragma unroll
                for (int m = 0; m < 2; m++) {
                    asm volatile(
                        "mma.sync.aligned.m16n8k8.row.col.f32.tf32.tf32.f32 "
                        "{%0,%1,%2,%3}, {%4,%5,%6,%7}, {%8,%9}, {%0,%1,%2,%3};"
                        : "+f"(acc[m][nt][0]), "+f"(acc[m][nt][1]),
                          "+f"(acc[m][nt][2]), "+f"(acc[m][nt][3])
                        : "r"(a[m][0]), "r"(a[m][1]), "r"(a[m][2]), "r"(a[m][3]),
                          "r"(b0), "r"(b1));
                }
            }
        }

        if (more) {
            unsigned* pd = psmem + (cur^1)*PBUF;
            #pragma unroll
            for (int it = 0; it < 4; it++)
                if (sok[it]) pd[psoff[it]] = pv[it];
            asm volatile("cp.async.wait_group 0;" ::: "memory");
        }
        __syncthreads();
    }

    // ---- writeback ----
    #pragma unroll
    for (int m = 0; m < 2; m++)
        #pragma unroll
        for (int nt = 0; nt < 4; nt++) {
            int co  = cog*32 + m*16 + g;
            int row = by0 + 2*rp + (nt & 1);
            int col = bx0 + (nt >> 1)*8 + 2*t;
            size_t base = (((size_t)b*CCH + co)*HH + row)*WW + col;
            if (outtf32) {
                unsigned* o = (unsigned*)outp;
                *(uint2*)&o[base]        = make_uint2(f2tf32(acc[m][nt][0]), f2tf32(acc[m][nt][1]));
                *(uint2*)&o[base + 8*HW] = make_uint2(f2tf32(acc[m][nt][2]), f2tf32(acc[m][nt][3]));
            } else {
                float* o = (float*)outp;
                *(float2*)&o[base]        = make_float2(acc[m][nt][0], acc[m][nt][1]);
                *(float2*)&o[base + 8*HW] = make_float2(acc[m][nt][2], acc[m][nt][3]);
            }
        }
}

// ---------------- attention GEMM (fp32) ----------------
__global__ __launch_bounds__(256)
void attn_gemm_kernel(const float* __restrict__ q, const float* __restrict__ k,
                      float* __restrict__ attn)
{
    const int p = blockIdx.x;        // 0..8
    const int b = blockIdx.y;        // 0..7
    const int i = p/3, j = p - 3*(p/3);
    const int tid = threadIdx.y*16 + threadIdx.x;

    __shared__ float Qs[16][96];
    __shared__ float Ks[16][96];

    float acc[6][6];
    #pragma unroll
    for (int r=0;r<6;r++)
        #pragma unroll
        for (int s=0;s<6;s++) acc[r][s]=0.f;

    for (int l0 = 0; l0 < 1024; l0 += 16) {
        #pragma unroll
        for (int it = 0; it < 6; it++) {
            int e = tid + it*256;
            int kk = e/96, c = e - kk*96;
            int l = l0 + kk;
            int gh = 3*(l>>5) + i, gw = 3*(l&31) + j;
            size_t off = ((size_t)(b*CCH + c)*HH + gh)*WW + gw;
            Qs[kk][c] = q[off];
            Ks[kk][c] = k[off];
        }
        __syncthreads();
        #pragma unroll
        for (int kk=0; kk<16; kk++) {
            float rq[6], rk[6];
            #pragma unroll
            for (int r=0;r<6;r++) {
                rq[r] = Qs[kk][threadIdx.y*6 + r];
                rk[r] = Ks[kk][threadIdx.x*6 + r];
            }
            #pragma unroll
            for (int r=0;r<6;r++)
                #pragma unroll
                for (int s=0;s<6;s++)
                    acc[r][s] = fmaf(rq[r], rk[s], acc[r][s]);
        }
        __syncthreads();
    }
    #pragma unroll
    for (int r=0;r<6;r++)
        #pragma unroll
        for (int s=0;s<6;s++) {
            int cq = threadIdx.y*6 + r, ck = threadIdx.x*6 + s;
            attn[((size_t)(b*CCH + ck)*CCH + cq)*9 + p] = acc[r][s];
        }
}

// ---------------- softmax over 864 per (b, ck) row ----------------
__global__ __launch_bounds__(256)
void softmax_kernel(float* __restrict__ attn)
{
    float* row = attn + (size_t)blockIdx.x * 864;
    const float scale = 0.034020690871988585f;   // 1/sqrt(864)
    const int tid = threadIdx.x;
    __shared__ float red[256];

    float v[4];
    float mx = -1e30f;
    #pragma unroll
    for (int it=0; it<4; it++) {
        int idx = tid + it*256;
        v[it] = (idx < 864) ? row[idx]*scale : -1e30f;
        mx = fmaxf(mx, v[it]);
    }
    red[tid] = mx; __syncthreads();
    for (int s=128; s>0; s>>=1) { if (tid<s) red[tid]=fmaxf(red[tid],red[tid+s]); __syncthreads(); }
    mx = red[0]; __syncthreads();

    float sum = 0.f;
    #pragma unroll
    for (int it=0; it<4; it++) {
        int idx = tid + it*256;
        v[it] = (idx < 864) ? expf(v[it]-mx) : 0.f;
        sum += v[it];
    }
    red[tid] = sum; __syncthreads();
    for (int s=128; s>0; s>>=1) { if (tid<s) red[tid]+=red[tid+s]; __syncthreads(); }
    float inv = 1.f/red[0];

    #pragma unroll
    for (int it=0; it<4; it++) {
        int idx = tid + it*256;
        if (idx < 864) row[idx] = v[it]*inv;
    }
}

// ---------------- batchnorm statistics (biased var) ----------------
__global__ __launch_bounds__(256)
void bnstats_kernel(const float* __restrict__ y1, const float* __restrict__ y2,
                    const float* __restrict__ y3,
                    float* __restrict__ meanv, float* __restrict__ istdv)
{
    const int t = blockIdx.x / CCH, c = blockIdx.x - t*CCH;
    const float* src = (t==0) ? y1 : (t==1) ? y2 : y3;
    float s = 0.f, sq = 0.f;
    for (int e = threadIdx.x; e < BATCH*HW; e += 256) {
        int b = e / HW, hw = e - b*HW;
        float vv = src[((size_t)b*CCH + c)*HW + hw];
        s += vv; sq = fmaf(vv, vv, sq);
    }
    __shared__ float sh1[256], sh2[256];
    sh1[threadIdx.x]=s; sh2[threadIdx.x]=sq;
    __syncthreads();
    for (int st=128; st>0; st>>=1) {
        if (threadIdx.x < st) { sh1[threadIdx.x]+=sh1[threadIdx.x+st]; sh2[threadIdx.x]+=sh2[threadIdx.x+st]; }
        __syncthreads();
    }
    if (threadIdx.x==0) {
        const float invN = 1.f / (float)(BATCH*HW);
        float m = sh1[0]*invN;
        float var = sh2[0]*invN - m*m;
        meanv[blockIdx.x] = m;
        istdv[blockIdx.x] = rsqrtf(var + 1e-5f);
    }
}

// ---------------- final fuse: out = (x+y, x) ----------------
__global__ __launch_bounds__(256)
void finalize_kernel(const float* __restrict__ x1, const float* __restrict__ x2,
                     const float* __restrict__ y1, const float* __restrict__ y2,
                     const float* __restrict__ y3,
                     const float* __restrict__ meanv, const float* __restrict__ istdv,
                     float* __restrict__ out, int writeSecond)
{
    int idx = blockIdx.x*256 + threadIdx.x;
    if (idx >= N1OUT) return;
    int hw = idx % HW;
    int c  = (idx / HW) % (2*CCH);
    int b  = idx / (HW*2*CCH);
    float xv, yv;
    if (c < CCH) {
        size_t off = ((size_t)b*CCH + c)*HW + hw;
        xv = x1[off];
        float a = (y1[off]-meanv[c])       * istdv[c];
        float g = (y2[off]-meanv[CCH+c])   * istdv[CCH+c];
        yv = a*g;
    } else {
        int cc = c - CCH;
        size_t off = ((size_t)b*CCH + cc)*HW + hw;
        xv = x2[off];
        yv = (y3[off]-meanv[2*CCH+cc]) * istdv[2*CCH+cc];
    }
    out[idx] = xv + yv;
    if (writeSecond) out[N1OUT + idx] = xv;
}

// ---------------- launch ----------------
extern "C" void kernel_launch(void* const* d_in, const int* in_sizes, int n_in,
                              void* d_out, int out_size)
{
    const float* x1  = (const float*)d_in[0];
    const float* x2  = (const float*)d_in[1];
    const float* w1  = (const float*)d_in[2];
    const float* w2  = (const float*)d_in[3];
    const float* wa1 = (const float*)d_in[4];
    const float* wa2 = (const float*)d_in[5];
    const float* wa3 = (const float*)d_in[6];
    float* out = (float*)d_out;

    float *y1,*y2,*q,*k,*y3,*attn,*meanv,*istdv;
    unsigned *x1t,*x2t,*vt,*w1t,*w2t,*wa1t,*wa2t,*wa3t,*wat;
    cudaGetSymbolAddress((void**)&y1,   g_y1);
    cudaGetSymbolAddress((void**)&y2,   g_y2);
    cudaGetSymbolAddress((void**)&q,    g_q);
    cudaGetSymbolAddress((void**)&k,    g_k);
    cudaGetSymbolAddress((void**)&y3,   g_y3);
    cudaGetSymbolAddress((void**)&attn, g_attn);
    cudaGetSymbolAddress((void**)&meanv,g_mean);
    cudaGetSymbolAddress((void**)&istdv,g_istd);
    cudaGetSymbolAddress((void**)&x1t,  g_x1t);
    cudaGetSymbolAddress((void**)&x2t,  g_x2t);
    cudaGetSymbolAddress((void**)&vt,   g_vt);
    cudaGetSymbolAddress((void**)&w1t,  g_w1t);
    cudaGetSymbolAddress((void**)&w2t,  g_w2t);
    cudaGetSymbolAddress((void**)&wa1t, g_wa1t);
    cudaGetSymbolAddress((void**)&wa2t, g_wa2t);
    cudaGetSymbolAddress((void**)&wa3t, g_wa3t);
    cudaGetSymbolAddress((void**)&wat,  g_wat);

    static int smem_set = 0;
    const int CONV_SMEM = (2*WCH2 + 2*PBUF) * 4;   // 68096 B
    if (!smem_set) {
        cudaFuncSetAttribute(conv3x3_tc3_kernel,
                             cudaFuncAttributeMaxDynamicSharedMemorySize, CONV_SMEM);
        smem_set = 1;
    }

    // 1. inputs -> tf32 (one launch)
    cvt_all_kernel<<<dim3((NPIX+255)/256, 2), 256>>>(x1, x2, x1t, x2t);

    // 2. all fixed weights -> fragment layout (one launch)
    wprep_all_kernel<<<dim3((24*WCH2+255)/256, 5), 256>>>(
        w1, w2, wa1, wa2, wa3, w1t, w2t, wa1t, wa2t, wa3t);

    dim3 tcgrid(72, 1, 8);   // 12 row-tiles x 6 col-tiles, 8 batches

    // 3. convs
    conv3x3_tc3_kernel<<<tcgrid, 384, CONV_SMEM>>>(x1t, x1t, 96,  96, w1t,  0, y1, 0);
    conv3x3_tc3_kernel<<<tcgrid, 384, CONV_SMEM>>>(x2t, x2t, 96,  96, w2t,  0, y2, 0);
    conv3x3_tc3_kernel<<<tcgrid, 384, CONV_SMEM>>>(x1t, x2t, 96, 192, wa1t, 0, q, 0);
    conv3x3_tc3_kernel<<<tcgrid, 384, CONV_SMEM>>>(x1t, x2t, 96, 192, wa2t, 0, k, 0);
    conv3x3_tc3_kernel<<<tcgrid, 384, CONV_SMEM>>>(x1t, x2t, 96, 192, wa3t, 0, vt, 1);  // v -> tf32 直接

    // 4. attention weights
    dim3 cblk(16,16);
    attn_gemm_kernel<<<dim3(9,8), cblk>>>(q, k, attn);
    softmax_kernel<<<BATCH*CCH, 256>>>(attn);
    wprep_attn_kernel<<<dim3((12*WCH2+255)/256, 1, BATCH), 256>>>(attn, wat);

    // 5. attn @ v_unf == per-batch 3x3 conv
    conv3x3_tc3_kernel<<<tcgrid, 384, CONV_SMEM>>>(vt, vt, 96, 96, wat, 12L*WCH2, y3, 0);

    // 6. batchnorm stats + fused epilogue
    bnstats_kernel<<<3*CCH, 256>>>(y1, y2, y3, meanv, istdv);
    int writeSecond = (out_size >= 2*N1OUT) ? 1 : 0;
    finalize_kernel<<<(N1OUT + 255)/256, 256>>>(x1, x2, y1, y2, y3, meanv, istdv, out, writeSecond);
}

// round 7
// speedup vs baseline: 1.4554x; 1.4554x over previous
#include <cuda_runtime.h>
#include <cuda_fp16.h>
#include <math.h>

#define BATCH 8
#define CCH 96
#define HH 96
#define WW 96
#define HW (HH*WW)                 // 9216
#define NPIX 7077888               // 8*96*96*96
#define NPIX2 (NPIX/2)
#define N1OUT 14155776             // 8*192*96*96

// weight layout: [chunk16ci][tap(9)][cotile(6)][lane(32)][4 frag words(half2)]
#define WCH2  6912                 // words per 16-ci chunk = 9*6*32*4
// patch smem: [ci2&3][row(10)][colpair] word=half2(2ci2,2ci2+1); pair (ci2, ci2+4) adjacent
#define PRS2  40
#define PCIS  400
#define PBUF  1600

// ---------------- scratch (static __device__, no allocation) ----------------
__device__ float g_y1[NPIX];
__device__ float g_y2[NPIX];
__device__ float g_q [NPIX];
__device__ float g_k [NPIX];
__device__ float g_v [NPIX];
__device__ float g_y3[NPIX];
__device__ float g_attn[BATCH*CCH*CCH*9];   // [b][ck][cq][p]
__device__ float g_mean[3*CCH];
__device__ float g_istd[3*CCH];

// ci-pair-interleaved half2 inputs: word[(b*48+ci2)*HW+hw] = {c=2ci2, c=2ci2+1}
__device__ __align__(16) unsigned g_x1h[NPIX2];
__device__ __align__(16) unsigned g_x2h[NPIX2];
__device__ __align__(16) unsigned g_vh [NPIX2];
// fragment-order fp16 weights
__device__ __align__(16) unsigned g_w1h [6*WCH2];
__device__ __align__(16) unsigned g_w2h [6*WCH2];
__device__ __align__(16) unsigned g_wa1h[12*WCH2];
__device__ __align__(16) unsigned g_wa2h[12*WCH2];
__device__ __align__(16) unsigned g_wa3h[12*WCH2];
__device__ __align__(16) unsigned g_wath[BATCH*6*WCH2];

__device__ __forceinline__ unsigned packh2(float a, float b) {
    __half2 h = __floats2half2_rn(a, b);
    return *(unsigned*)&h;
}

// ---------------- fp32 -> ci-pair-interleaved half2 ----------------
// grid.y: 0 -> (s1,d1), 1 -> (s2,d2)
__global__ __launch_bounds__(256)
void cvt_pair_kernel(const float* __restrict__ s1, unsigned* __restrict__ d1,
                     const float* __restrict__ s2, unsigned* __restrict__ d2)
{
    const float* src = blockIdx.y ? s2 : s1;
    unsigned* dst    = blockIdx.y ? d2 : d1;
    int e = blockIdx.x*256 + threadIdx.x;
    if (e >= NPIX2) return;
    int b = e / (48*HW), r = e - b*48*HW;
    int ci2 = r / HW, hw = r - ci2*HW;
    size_t off = ((size_t)b*CCH + 2*ci2)*HW + hw;
    dst[e] = packh2(src[off], src[off + HW]);
}

// ---------------- weight pre-transform (m16n8k16 fragment order) -----------
// word e: chunk=e/WCH2; rm=e%WCH2; w=rm&3; lane=(rm>>2)&31; mtap=rm>>7;
// tap=mtap/6; mt=mtap%6; g=lane>>2; t=lane&3
// co = mt*16+g+(w&1)*8 ; ci = chunk*16 + 2t + ((w>>1)&1)*8 ; pack (ci, ci+1)
__global__ __launch_bounds__(256)
void wprep_all_kernel(const float* __restrict__ w1, const float* __restrict__ w2,
                      const float* __restrict__ wa1, const float* __restrict__ wa2,
                      const float* __restrict__ wa3,
                      unsigned* __restrict__ d1, unsigned* __restrict__ d2,
                      unsigned* __restrict__ d3, unsigned* __restrict__ d4,
                      unsigned* __restrict__ d5)
{
    const int id = blockIdx.y;
    const float* src; unsigned* dst; int cin;
    if      (id == 0) { src = w1;  dst = d1; cin = 96;  }
    else if (id == 1) { src = w2;  dst = d2; cin = 96;  }
    else if (id == 2) { src = wa1; dst = d3; cin = 192; }
    else if (id == 3) { src = wa2; dst = d4; cin = 192; }
    else              { src = wa3; dst = d5; cin = 192; }
    const int nwords = (cin >> 4) * WCH2;
    int e = blockIdx.x*256 + threadIdx.x;
    if (e >= nwords) return;
    int chunk = e / WCH2, rm = e - chunk*WCH2;
    int w = rm & 3, lane = (rm >> 2) & 31, mtap = rm >> 7;
    int tap = mtap / 6, mt = mtap - 6*tap;
    int g = lane >> 2, t = lane & 3;
    int co = mt*16 + g + (w & 1)*8;
    int ci = chunk*16 + 2*t + ((w >> 1) & 1)*8;
    dst[e] = packh2(src[((size_t)co*cin + ci)*9 + tap],
                    src[((size_t)co*cin + ci + 1)*9 + tap]);
}

// attn weights -> fragment order, per batch (cin=96 -> 6 chunks)
__global__ __launch_bounds__(256)
void wprep_attn_kernel(const float* __restrict__ attn, unsigned* __restrict__ dst)
{
    const int b = blockIdx.z;
    int e = blockIdx.x*256 + threadIdx.x;
    if (e >= 6*WCH2) return;
    int chunk = e / WCH2, rm = e - chunk*WCH2;
    int w = rm & 3, lane = (rm >> 2) & 31, mtap = rm >> 7;
    int tap = mtap / 6, mt = mtap - 6*tap;
    int g = lane >> 2, t = lane & 3;
    int co = mt*16 + g + (w & 1)*8;
    int ci = chunk*16 + 2*t + ((w >> 1) & 1)*8;
    const float* a = attn + (size_t)b*CCH*CCH*9;
    dst[(size_t)b*6*WCH2 + e] = packh2(a[((size_t)co*CCH + ci)*9 + tap],
                                       a[((size_t)co*CCH + ci + 1)*9 + tap]);
}

// ---------------- tensor-core 3x3 conv, fp16 m16n8k16 ----------------------
// block: 384 thr (12 warps) -> tile 96co x 128px (8 rows x 16 cols)
// warp: cog=wid>>2 (32 co = 2 m-tiles), rp=wid&3 (rows 2rp,2rp+1); 4 n-tiles
// csplit2/cin2 are in ci2 (channel-pair) units; chunk = 8 ci2 planes = 16 ci
__global__ __launch_bounds__(384, 2)
void conv3x3_fp16_kernel(const unsigned* __restrict__ inAh, const unsigned* __restrict__ inBh,
                         int csplit2, int cin2,
                         const unsigned* __restrict__ wh, long wbstride,
                         float* __restrict__ out)
{
    extern __shared__ unsigned dsm[];        // [2*WCH2 weights][2*PBUF patch]
    const int tid  = threadIdx.x;
    const int lane = tid & 31, wid = tid >> 5;
    const int g = lane >> 2, t = lane & 3;
    const int cog = wid >> 2;                // 0..2
    const int rp  = wid & 3;                 // 0..3
    const int b   = blockIdx.z;
    const int byk = blockIdx.x / 6, bxk = blockIdx.x - 6*byk;
    const int by0 = byk*8, bx0 = bxk*16;

    const unsigned smem_b = (unsigned)__cvta_generic_to_shared(dsm);
    unsigned* psmem = dsm + 2*WCH2;

    // ---- hoisted patch geometry (1440 words = 8 ci2-planes x 10r x 18c) ----
    int pgoff[4], psoff[4], pci[4];
    bool lok[4], sok[4];
    #pragma unroll
    for (int it = 0; it < 4; it++) {
        int e = tid + it*384;
        int ci = e / 180, r2 = e - ci*180;
        int row = r2 / 18, col = r2 - row*18;
        int gh = by0 + row - 1, gw = bx0 + col - 1;
        bool inp = (e < 1440);
        bool ok = inp && gh >= 0 && gh < HH && gw >= 0 && gw < WW;
        lok[it] = ok; sok[it] = inp;
        pgoff[it] = ok ? gh*WW + gw : 0;
        psoff[it] = inp ? (ci & 3)*PCIS + row*PRS2 + col*2 + (ci >> 2) : 0;
        pci[it]   = ci;
    }

    const unsigned* wsrc0 = wh + (size_t)wbstride*b;

    // ---- prologue: chunk 0 into buffer 0 ----
    #pragma unroll
    for (int k2 = 0; k2 < 5; k2++) {
        int idx = tid + k2*384;
        if (idx < WCH2/4)
            asm volatile("cp.async.cg.shared.global [%0], [%1], 16;"
                         :: "r"(smem_b + idx*16), "l"(wsrc0 + idx*4) : "memory");
    }
    asm volatile("cp.async.commit_group;" ::: "memory");
    {
        unsigned pv[4];
        #pragma unroll
        for (int it = 0; it < 4; it++) {
            int gci = pci[it];
            const unsigned* src = (gci < csplit2)
                ? inAh + ((size_t)b*csplit2 + gci)*HW
                : inBh + ((size_t)b*(cin2-csplit2) + (gci-csplit2))*HW;
            pv[it] = lok[it] ? src[pgoff[it]] : 0u;
        }
        #pragma unroll
        for (int it = 0; it < 4; it++)
            if (sok[it]) psmem[psoff[it]] = pv[it];
    }
    asm volatile("cp.async.wait_group 0;" ::: "memory");
    __syncthreads();

    float acc[2][4][4];
    #pragma unroll
    for (int m=0;m<2;m++)
        #pragma unroll
        for (int nt=0;nt<4;nt++)
            #pragma unroll
            for (int r=0;r<4;r++) acc[m][nt][r] = 0.f;

    const int nchunk = cin2 >> 3;
    for (int ch = 0; ch < nchunk; ch++) {
        const int cur = ch & 1;
        const bool more = (ch + 1 < nchunk);

        // stage next chunk
        unsigned pv[4];
        if (more) {
            const unsigned* wsrc = wsrc0 + (size_t)(ch+1)*WCH2;
            const unsigned wdst = smem_b + (cur^1)*WCH2*4;
            #pragma unroll
            for (int k2 = 0; k2 < 5; k2++) {
                int idx = tid + k2*384;
                if (idx < WCH2/4)
                    asm volatile("cp.async.cg.shared.global [%0], [%1], 16;"
                                 :: "r"(wdst + idx*16), "l"(wsrc + idx*4) : "memory");
            }
            asm volatile("cp.async.commit_group;" ::: "memory");
            const int ci0 = (ch+1) << 3;
            #pragma unroll
            for (int it = 0; it < 4; it++) {
                int gci = ci0 + pci[it];
                const unsigned* src = (gci < csplit2)
                    ? inAh + ((size_t)b*csplit2 + gci)*HW
                    : inBh + ((size_t)b*(cin2-csplit2) + (gci-csplit2))*HW;
                pv[it] = lok[it] ? src[pgoff[it]] : 0u;
            }
        }

        // ---- mma on current buffers ----
        const unsigned wbase = smem_b + cur*WCH2*4;
        const unsigned pbase = smem_b + (2*WCH2 + cur*PBUF)*4;
        #pragma unroll
        for (int tap = 0; tap < 9; tap++) {
            const int i = tap/3, j = tap - 3*(tap/3);
            unsigned a[2][4];
            #pragma unroll
            for (int m = 0; m < 2; m++) {
                const int mt = cog*2 + m;
                asm volatile("ld.shared.v4.b32 {%0,%1,%2,%3}, [%4];"
                    : "=r"(a[m][0]), "=r"(a[m][1]), "=r"(a[m][2]), "=r"(a[m][3])
                    : "r"(wbase + (((tap*6 + mt)*32 + lane)*16)));
            }
            #pragma unroll
            for (int nt = 0; nt < 4; nt++) {
                const int py = 2*rp + (nt & 1);
                const int cb2 = (nt >> 1) * 8;
                unsigned b0, b1;
                asm volatile("ld.shared.v2.b32 {%0,%1}, [%2];"
                    : "=r"(b0), "=r"(b1)
                    : "r"(pbase + (t*PCIS + (py+i)*PRS2 + (cb2+j+g)*2)*4));
                #pragma unroll
                for (int m = 0; m < 2; m++) {
                    asm volatile(
                        "mma.sync.aligned.m16n8k16.row.col.f32.f16.f16.f32 "
                        "{%0,%1,%2,%3}, {%4,%5,%6,%7}, {%8,%9}, {%0,%1,%2,%3};"
                        : "+f"(acc[m][nt][0]), "+f"(acc[m][nt][1]),
                          "+f"(acc[m][nt][2]), "+f"(acc[m][nt][3])
                        : "r"(a[m][0]), "r"(a[m][1]), "r"(a[m][2]), "r"(a[m][3]),
                          "r"(b0), "r"(b1));
                }
            }
        }

        if (more) {
            unsigned* pd = psmem + (cur^1)*PBUF;
            #pragma unroll
            for (int it = 0; it < 4; it++)
                if (sok[it]) pd[psoff[it]] = pv[it];
            asm volatile("cp.async.wait_group 0;" ::: "memory");
        }
        __syncthreads();
    }

    // ---- writeback ----
    #pragma unroll
    for (int m = 0; m < 2; m++)
        #pragma unroll
        for (int nt = 0; nt < 4; nt++) {
            int co  = cog*32 + m*16 + g;
            int row = by0 + 2*rp + (nt & 1);
            int col = bx0 + (nt >> 1)*8 + 2*t;
            size_t base = (((size_t)b*CCH + co)*HH + row)*WW + col;
            *(float2*)&out[base]        = make_float2(acc[m][nt][0], acc[m][nt][1]);
            *(float2*)&out[base + 8*HW] = make_float2(acc[m][nt][2], acc[m][nt][3]);
        }
}

// ---------------- attention GEMM (fp32) ----------------
__global__ __launch_bounds__(256)
void attn_gemm_kernel(const float* __restrict__ q, const float* __restrict__ k,
                      float* __restrict__ attn)
{
    const int p = blockIdx.x;        // 0..8
    const int b = blockIdx.y;        // 0..7
    const int i = p/3, j = p - 3*(p/3);
    const int tid = threadIdx.y*16 + threadIdx.x;

    __shared__ float Qs[16][96];
    __shared__ float Ks[16][96];

    float acc[6][6];
    #pragma unroll
    for (int r=0;r<6;r++)
        #pragma unroll
        for (int s=0;s<6;s++) acc[r][s]=0.f;

    for (int l0 = 0; l0 < 1024; l0 += 16) {
        #pragma unroll
        for (int it = 0; it < 6; it++) {
            int e = tid + it*256;
            int kk = e/96, c = e - kk*96;
            int l = l0 + kk;
            int gh = 3*(l>>5) + i, gw = 3*(l&31) + j;
            size_t off = ((size_t)(b*CCH + c)*HH + gh)*WW + gw;
            Qs[kk][c] = q[off];
            Ks[kk][c] = k[off];
        }
        __syncthreads();
        #pragma unroll
        for (int kk=0; kk<16; kk++) {
            float rq[6], rk[6];
            #pragma unroll
            for (int r=0;r<6;r++) {
                rq[r] = Qs[kk][threadIdx.y*6 + r];
                rk[r] = Ks[kk][threadIdx.x*6 + r];
            }
            #pragma unroll
            for (int r=0;r<6;r++)
                #pragma unroll
                for (int s=0;s<6;s++)
                    acc[r][s] = fmaf(rq[r], rk[s], acc[r][s]);
        }
        __syncthreads();
    }
    #pragma unroll
    for (int r=0;r<6;r++)
        #pragma unroll
        for (int s=0;s<6;s++) {
            int cq = threadIdx.y*6 + r, ck = threadIdx.x*6 + s;
            attn[((size_t)(b*CCH + ck)*CCH + cq)*9 + p] = acc[r][s];
        }
}

// ---------------- softmax over 864 per (b, ck) row ----------------
__global__ __launch_bounds__(256)
void softmax_kernel(float* __restrict__ attn)
{
    float* row = attn + (size_t)blockIdx.x * 864;
    const float scale = 0.034020690871988585f;   // 1/sqrt(864)
    const int tid = threadIdx.x;
    __shared__ float red[256];

    float v[4];
    float mx = -1e30f;
    #pragma unroll
    for (int it=0; it<4; it++) {
        int idx = tid + it*256;
        v[it] = (idx < 864) ? row[idx]*scale : -1e30f;
        mx = fmaxf(mx, v[it]);
    }
    red[tid] = mx; __syncthreads();
    for (int s=128; s>0; s>>=1) { if (tid<s) red[tid]=fmaxf(red[tid],red[tid+s]); __syncthreads(); }
    mx = red[0]; __syncthreads();

    float sum = 0.f;
    #pragma unroll
    for (int it=0; it<4; it++) {
        int idx = tid + it*256;
        v[it] = (idx < 864) ? expf(v[it]-mx) : 0.f;
        sum += v[it];
    }
    red[tid] = sum; __syncthreads();
    for (int s=128; s>0; s>>=1) { if (tid<s) red[tid]+=red[tid+s]; __syncthreads(); }
    float inv = 1.f/red[0];

    #pragma unroll
    for (int it=0; it<4; it++) {
        int idx = tid + it*256;
        if (idx < 864) row[idx] = v[it]*inv;
    }
}

// ---------------- batchnorm statistics (biased var) ----------------
__global__ __launch_bounds__(256)
void bnstats_kernel(const float* __restrict__ y1, const float* __restrict__ y2,
                    const float* __restrict__ y3,
                    float* __restrict__ meanv, float* __restrict__ istdv)
{
    const int t = blockIdx.x / CCH, c = blockIdx.x - t*CCH;
    const float* src = (t==0) ? y1 : (t==1) ? y2 : y3;
    float s = 0.f, sq = 0.f;
    for (int e = threadIdx.x; e < BATCH*HW; e += 256) {
        int b = e / HW, hw = e - b*HW;
        float vv = src[((size_t)b*CCH + c)*HW + hw];
        s += vv; sq = fmaf(vv, vv, sq);
    }
    __shared__ float sh1[256], sh2[256];
    sh1[threadIdx.x]=s; sh2[threadIdx.x]=sq;
    __syncthreads();
    for (int st=128; st>0; st>>=1) {
        if (threadIdx.x < st) { sh1[threadIdx.x]+=sh1[threadIdx.x+st]; sh2[threadIdx.x]+=sh2[threadIdx.x+st]; }
        __syncthreads();
    }
    if (threadIdx.x==0) {
        const float invN = 1.f / (float)(BATCH*HW);
        float m = sh1[0]*invN;
        float var = sh2[0]*invN - m*m;
        meanv[blockIdx.x] = m;
        istdv[blockIdx.x] = rsqrtf(var + 1e-5f);
    }
}

// ---------------- final fuse: out = (x+y, x) ----------------
__global__ __launch_bounds__(256)
void finalize_kernel(const float* __restrict__ x1, const float* __restrict__ x2,
                     const float* __restrict__ y1, const float* __restrict__ y2,
                     const float* __restrict__ y3,
                     const float* __restrict__ meanv, const float* __restrict__ istdv,
                     float* __restrict__ out, int writeSecond)
{
    int idx = blockIdx.x*256 + threadIdx.x;
    if (idx >= N1OUT) return;
    int hw = idx % HW;
    int c  = (idx / HW) % (2*CCH);
    int b  = idx / (HW*2*CCH);
    float xv, yv;
    if (c < CCH) {
        size_t off = ((size_t)b*CCH + c)*HW + hw;
        xv = x1[off];
        float a = (y1[off]-meanv[c])       * istdv[c];
        float g = (y2[off]-meanv[CCH+c])   * istdv[CCH+c];
        yv = a*g;
    } else {
        int cc = c - CCH;
        size_t off = ((size_t)b*CCH + cc)*HW + hw;
        xv = x2[off];
        yv = (y3[off]-meanv[2*CCH+cc]) * istdv[2*CCH+cc];
    }
    out[idx] = xv + yv;
    if (writeSecond) out[N1OUT + idx] = xv;
}

// ---------------- launch ----------------
extern "C" void kernel_launch(void* const* d_in, const int* in_sizes, int n_in,
                              void* d_out, int out_size)
{
    const float* x1  = (const float*)d_in[0];
    const float* x2  = (const float*)d_in[1];
    const float* w1  = (const float*)d_in[2];
    const float* w2  = (const float*)d_in[3];
    const float* wa1 = (const float*)d_in[4];
    const float* wa2 = (const float*)d_in[5];
    const float* wa3 = (const float*)d_in[6];
    float* out = (float*)d_out;

    float *y1,*y2,*q,*k,*v,*y3,*attn,*meanv,*istdv;
    unsigned *x1h,*x2h,*vh,*w1h,*w2h,*wa1h,*wa2h,*wa3h,*wath;
    cudaGetSymbolAddress((void**)&y1,   g_y1);
    cudaGetSymbolAddress((void**)&y2,   g_y2);
    cudaGetSymbolAddress((void**)&q,    g_q);
    cudaGetSymbolAddress((void**)&k,    g_k);
    cudaGetSymbolAddress((void**)&v,    g_v);
    cudaGetSymbolAddress((void**)&y3,   g_y3);
    cudaGetSymbolAddress((void**)&attn, g_attn);
    cudaGetSymbolAddress((void**)&meanv,g_mean);
    cudaGetSymbolAddress((void**)&istdv,g_istd);
    cudaGetSymbolAddress((void**)&x1h,  g_x1h);
    cudaGetSymbolAddress((void**)&x2h,  g_x2h);
    cudaGetSymbolAddress((void**)&vh,   g_vh);
    cudaGetSymbolAddress((void**)&w1h,  g_w1h);
    cudaGetSymbolAddress((void**)&w2h,  g_w2h);
    cudaGetSymbolAddress((void**)&wa1h, g_wa1h);
    cudaGetSymbolAddress((void**)&wa2h, g_wa2h);
    cudaGetSymbolAddress((void**)&wa3h, g_wa3h);
    cudaGetSymbolAddress((void**)&wath, g_wath);

    static int smem_set = 0;
    const int CONV_SMEM = (2*WCH2 + 2*PBUF) * 4;   // 68096 B
    if (!smem_set) {
        cudaFuncSetAttribute(conv3x3_fp16_kernel,
                             cudaFuncAttributeMaxDynamicSharedMemorySize, CONV_SMEM);
        smem_set = 1;
    }

    // 1. inputs -> interleaved half2 (one launch, two streams)
    cvt_pair_kernel<<<dim3((NPIX2+255)/256, 2), 256>>>(x1, x1h, x2, x2h);

    // 2. all fixed weights -> fp16 fragment layout (one launch)
    wprep_all_kernel<<<dim3((12*WCH2+255)/256, 5), 256>>>(
        w1, w2, wa1, wa2, wa3, w1h, w2h, wa1h, wa2h, wa3h);

    dim3 tcgrid(72, 1, 8);   // 12 row-tiles x 6 col-tiles, 8 batches

    // 3. convs (fp16 tensor cores)
    conv3x3_fp16_kernel<<<tcgrid, 384, CONV_SMEM>>>(x1h, x1h, 48, 48, w1h,  0, y1);
    conv3x3_fp16_kernel<<<tcgrid, 384, CONV_SMEM>>>(x2h, x2h, 48, 48, w2h,  0, y2);
    conv3x3_fp16_kernel<<<tcgrid, 384, CONV_SMEM>>>(x1h, x2h, 48, 96, wa1h, 0, q);
    conv3x3_fp16_kernel<<<tcgrid, 384, CONV_SMEM>>>(x1h, x2h, 48, 96, wa2h, 0, k);
    conv3x3_fp16_kernel<<<tcgrid, 384, CONV_SMEM>>>(x1h, x2h, 48, 96, wa3h, 0, v);

    // 4. attention weights
    dim3 cblk(16,16);
    attn_gemm_kernel<<<dim3(9,8), cblk>>>(q, k, attn);
    softmax_kernel<<<BATCH*CCH, 256>>>(attn);

    // 5. v -> half2 ; attn weights -> fp16 fragment layout (per batch)
    cvt_pair_kernel<<<dim3((NPIX2+255)/256, 1), 256>>>(v, vh, v, vh);
    wprep_attn_kernel<<<dim3((6*WCH2+255)/256, 1, BATCH), 256>>>(attn, wath);

    // 6. attn @ v_unf == per-batch 3x3 conv
    conv3x3_fp16_kernel<<<tcgrid, 384, CONV_SMEM>>>(vh, vh, 48, 48, wath, 6L*WCH2, y3);

    // 7. batchnorm stats + fused epilogue
    bnstats_kernel<<<3*CCH, 256>>>(y1, y2, y3, meanv, istdv);
    int writeSecond = (out_size >= 2*N1OUT) ? 1 : 0;
    finalize_kernel<<<(N1OUT + 255)/256, 256>>>(x1, x2, y1, y2, y3, meanv, istdv, out, writeSecond);
}

// round 9
// speedup vs baseline: 1.4593x; 1.0027x over previous
#include <cuda_runtime.h>
#include <cuda_fp16.h>
#include <math.h>

#define BATCH 8
#define CCH 96
#define HH 96
#define WW 96
#define HW (HH*WW)                 // 9216
#define NPIX 7077888               // 8*96*96*96
#define NPIX2 (NPIX/2)
#define N1OUT 14155776             // 8*192*96*96

// weight layout: [chunk16ci][tap(9)][cotile(6)][lane(32)][4 frag words(half2)]
#define WCH2  6912                 // words per 16-ci chunk = 9*6*32*4
// patch smem: [ci2&3][row(10)][colpair] word=half2(2ci2,2ci2+1); pair (ci2, ci2+4) adjacent
#define PRS2  40
#define PCIS  400
#define PBUF  1600

// ---------------- scratch (static __device__, no allocation) ----------------
__device__ float g_y1[NPIX];
__device__ float g_y2[NPIX];
__device__ float g_q [NPIX];
__device__ float g_k [NPIX];
__device__ float g_v [NPIX];
__device__ float g_y3[NPIX];
__device__ float g_attn[BATCH*CCH*CCH*9];   // [b][ck][cq][p]
__device__ float g_mean[3*CCH];
__device__ float g_istd[3*CCH];

// ci-pair-interleaved half2 inputs: word[(b*48+ci2)*HW+hw] = {c=2ci2, c=2ci2+1}
__device__ __align__(16) unsigned g_x1h[NPIX2];
__device__ __align__(16) unsigned g_x2h[NPIX2];
__device__ __align__(16) unsigned g_vh [NPIX2];
// fragment-order fp16 weights
__device__ __align__(16) unsigned g_w1h [6*WCH2];
__device__ __align__(16) unsigned g_w2h [6*WCH2];
__device__ __align__(16) unsigned g_wa1h[12*WCH2];
__device__ __align__(16) unsigned g_wa2h[12*WCH2];
__device__ __align__(16) unsigned g_wa3h[12*WCH2];
__device__ __align__(16) unsigned g_wath[BATCH*6*WCH2];

__device__ __forceinline__ unsigned packh2(float a, float b) {
    __half2 h = __floats2half2_rn(a, b);
    return *(unsigned*)&h;
}

// ---------------- fp32 -> ci-pair-interleaved half2 ----------------
__global__ __launch_bounds__(256)
void cvt_pair_kernel(const float* __restrict__ s1, unsigned* __restrict__ d1,
                     const float* __restrict__ s2, unsigned* __restrict__ d2)
{
    const float* src = blockIdx.y ? s2 : s1;
    unsigned* dst    = blockIdx.y ? d2 : d1;
    int e = blockIdx.x*256 + threadIdx.x;
    if (e >= NPIX2) return;
    int b = e / (48*HW), r = e - b*48*HW;
    int ci2 = r / HW, hw = r - ci2*HW;
    size_t off = ((size_t)b*CCH + 2*ci2)*HW + hw;
    dst[e] = packh2(src[off], src[off + HW]);
}

// ---------------- weight pre-transform (m16n8k16 fragment order) -----------
__global__ __launch_bounds__(256)
void wprep_all_kernel(const float* __restrict__ w1, const float* __restrict__ w2,
                      const float* __restrict__ wa1, const float* __restrict__ wa2,
                      const float* __restrict__ wa3,
                      unsigned* __restrict__ d1, unsigned* __restrict__ d2,
                      unsigned* __restrict__ d3, unsigned* __restrict__ d4,
                      unsigned* __restrict__ d5)
{
    const int id = blockIdx.y;
    const float* src; unsigned* dst; int cin;
    if      (id == 0) { src = w1;  dst = d1; cin = 96;  }
    else if (id == 1) { src = w2;  dst = d2; cin = 96;  }
    else if (id == 2) { src = wa1; dst = d3; cin = 192; }
    else if (id == 3) { src = wa2; dst = d4; cin = 192; }
    else              { src = wa3; dst = d5; cin = 192; }
    const int nwords = (cin >> 4) * WCH2;
    int e = blockIdx.x*256 + threadIdx.x;
    if (e >= nwords) return;
    int chunk = e / WCH2, rm = e - chunk*WCH2;
    int w = rm & 3, lane = (rm >> 2) & 31, mtap = rm >> 7;
    int tap = mtap / 6, mt = mtap - 6*tap;
    int g = lane >> 2, t = lane & 3;
    int co = mt*16 + g + (w & 1)*8;
    int ci = chunk*16 + 2*t + ((w >> 1) & 1)*8;
    dst[e] = packh2(src[((size_t)co*cin + ci)*9 + tap],
                    src[((size_t)co*cin + ci + 1)*9 + tap]);
}

// attn weights -> fragment order, per batch (cin=96 -> 6 chunks)
__global__ __launch_bounds__(256)
void wprep_attn_kernel(const float* __restrict__ attn, unsigned* __restrict__ dst)
{
    const int b = blockIdx.z;
    int e = blockIdx.x*256 + threadIdx.x;
    if (e >= 6*WCH2) return;
    int chunk = e / WCH2, rm = e - chunk*WCH2;
    int w = rm & 3, lane = (rm >> 2) & 31, mtap = rm >> 7;
    int tap = mtap / 6, mt = mtap - 6*tap;
    int g = lane >> 2, t = lane & 3;
    int co = mt*16 + g + (w & 1)*8;
    int ci = chunk*16 + 2*t + ((w >> 1) & 1)*8;
    const float* a = attn + (size_t)b*CCH*CCH*9;
    dst[(size_t)b*6*WCH2 + e] = packh2(a[((size_t)co*CCH + ci)*9 + tap],
                                       a[((size_t)co*CCH + ci + 1)*9 + tap]);
}

// ---------------- tensor-core 3x3 conv, fp16 m16n8k16 ----------------------
// block: 192 thr (6 warps) -> tile 96co x 128px (8 rows x 16 cols)
// warp: cog=wid>>1 (32 co = 2 m-tiles), rp=wid&1 (rows 4rp..4rp+3); 8 n-tiles
// py = 4*rp + (nt&3), col-block cb2 = (nt>>2)*8
__global__ __launch_bounds__(192, 2)
void conv3x3_fp16_kernel(const unsigned* __restrict__ inAh, const unsigned* __restrict__ inBh,
                         int csplit2, int cin2,
                         const unsigned* __restrict__ wh, long wbstride,
                         float* __restrict__ out)
{
    extern __shared__ unsigned dsm[];        // [2*WCH2 weights][2*PBUF patch]
    const int tid  = threadIdx.x;
    const int lane = tid & 31, wid = tid >> 5;
    const int g = lane >> 2, t = lane & 3;
    const int cog = wid >> 1;                // 0..2
    const int rp  = wid & 1;                 // 0..1
    const int b   = blockIdx.z;
    const int byk = blockIdx.x / 6, bxk = blockIdx.x - 6*byk;
    const int by0 = byk*8, bx0 = bxk*16;

    const unsigned smem_b = (unsigned)__cvta_generic_to_shared(dsm);
    unsigned* psmem = dsm + 2*WCH2;

    // ---- hoisted patch geometry (1440 words = 8 ci2-planes x 10r x 18c) ----
    int pgoff[8], psoff[8], pci[8];
    bool lok[8], sok[8];
    #pragma unroll
    for (int it = 0; it < 8; it++) {
        int e = tid + it*192;
        int ci = e / 180, r2 = e - ci*180;
        int row = r2 / 18, col = r2 - row*18;
        int gh = by0 + row - 1, gw = bx0 + col - 1;
        bool inp = (e < 1440);
        bool ok = inp && gh >= 0 && gh < HH && gw >= 0 && gw < WW;
        lok[it] = ok; sok[it] = inp;
        pgoff[it] = ok ? gh*WW + gw : 0;
        psoff[it] = inp ? (ci & 3)*PCIS + row*PRS2 + col*2 + (ci >> 2) : 0;
        pci[it]   = ci;
    }

    const unsigned* wsrc0 = wh + (size_t)wbstride*b;

    // ---- prologue: chunk 0 into buffer 0 (1728 = 9*192 16B copies) ----
    #pragma unroll
    for (int k2 = 0; k2 < 9; k2++) {
        int idx = tid + k2*192;
        asm volatile("cp.async.cg.shared.global [%0], [%1], 16;"
                     :: "r"(smem_b + idx*16), "l"(wsrc0 + idx*4) : "memory");
    }
    asm volatile("cp.async.commit_group;" ::: "memory");
    {
        unsigned pv[8];
        #pragma unroll
        for (int it = 0; it < 8; it++) {
            int gci = pci[it];
            const unsigned* src = (gci < csplit2)
                ? inAh + ((size_t)b*csplit2 + gci)*HW
                : inBh + ((size_t)b*(cin2-csplit2) + (gci-csplit2))*HW;
            pv[it] = lok[it] ? src[pgoff[it]] : 0u;
        }
        #pragma unroll
        for (int it = 0; it < 8; it++)
            if (sok[it]) psmem[psoff[it]] = pv[it];
    }
    asm volatile("cp.async.wait_group 0;" ::: "memory");
    __syncthreads();

    float acc[2][8][4];
    #pragma unroll
    for (int m=0;m<2;m++)
        #pragma unroll
        for (int nt=0;nt<8;nt++)
            #pragma unroll
            for (int r=0;r<4;r++) acc[m][nt][r] = 0.f;

    const int nchunk = cin2 >> 3;
    for (int ch = 0; ch < nchunk; ch++) {
        const int cur = ch & 1;
        const bool more = (ch + 1 < nchunk);

        // stage next chunk
        unsigned pv[8];
        if (more) {
            const unsigned* wsrc = wsrc0 + (size_t)(ch+1)*WCH2;
            const unsigned wdst = smem_b + (cur^1)*WCH2*4;
            #pragma unroll
            for (int k2 = 0; k2 < 9; k2++) {
                int idx = tid + k2*192;
                asm volatile("cp.async.cg.shared.global [%0], [%1], 16;"
                             :: "r"(wdst + idx*16), "l"(wsrc + idx*4) : "memory");
            }
            asm volatile("cp.async.commit_group;" ::: "memory");
            const int ci0 = (ch+1) << 3;
            #pragma unroll
            for (int it = 0; it < 8; it++) {
                int gci = ci0 + pci[it];
                const unsigned* src = (gci < csplit2)
                    ? inAh + ((size_t)b*csplit2 + gci)*HW
                    : inBh + ((size_t)b*(cin2-csplit2) + (gci-csplit2))*HW;
                pv[it] = lok[it] ? src[pgoff[it]] : 0u;
            }
        }

        // ---- mma on current buffers ----
        const unsigned wbase = smem_b + cur*WCH2*4;
        const unsigned pbase = smem_b + (2*WCH2 + cur*PBUF)*4;
        #pragma unroll
        for (int tap = 0; tap < 9; tap++) {
            const int i = tap/3, j = tap - 3*(tap/3);
            unsigned a[2][4];
            #pragma unroll
            for (int m = 0; m < 2; m++) {
                const int mt = cog*2 + m;
                asm volatile("ld.shared.v4.b32 {%0,%1,%2,%3}, [%4];"
                    : "=r"(a[m][0]), "=r"(a[m][1]), "=r"(a[m][2]), "=r"(a[m][3])
                    : "r"(wbase + (((tap*6 + mt)*32 + lane)*16)));
            }
            #pragma unroll
            for (int nt = 0; nt < 8; nt++) {
                const int py = 4*rp + (nt & 3);
                const int cb2 = (nt >> 2) * 8;
                unsigned b0, b1;
                asm volatile("ld.shared.v2.b32 {%0,%1}, [%2];"
                    : "=r"(b0), "=r"(b1)
                    : "r"(pbase + (t*PCIS + (py+i)*PRS2 + (cb2+j+g)*2)*4));
                #pragma unroll
                for (int m = 0; m < 2; m++) {
                    asm volatile(
                        "mma.sync.aligned.m16n8k16.row.col.f32.f16.f16.f32 "
                        "{%0,%1,%2,%3}, {%4,%5,%6,%7}, {%8,%9}, {%0,%1,%2,%3};"
                        : "+f"(acc[m][nt][0]), "+f"(acc[m][nt][1]),
                          "+f"(acc[m][nt][2]), "+f"(acc[m][nt][3])
                        : "r"(a[m][0]), "r"(a[m][1]), "r"(a[m][2]), "r"(a[m][3]),
                          "r"(b0), "r"(b1));
                }
            }
        }

        if (more) {
            unsigned* pd = psmem + (cur^1)*PBUF;
            #pragma unroll
            for (int it = 0; it < 8; it++)
                if (sok[it]) pd[psoff[it]] = pv[it];
            asm volatile("cp.async.wait_group 0;" ::: "memory");
        }
        __syncthreads();
    }

    // ---- writeback ----
    #pragma unroll
    for (int m = 0; m < 2; m++)
        #pragma unroll
        for (int nt = 0; nt < 8; nt++) {
            int co  = cog*32 + m*16 + g;
            int row = by0 + 4*rp + (nt & 3);
            int col = bx0 + (nt >> 2)*8 + 2*t;
            size_t base = (((size_t)b*CCH + co)*HH + row)*WW + col;
            *(float2*)&out[base]        = make_float2(acc[m][nt][0], acc[m][nt][1]);
            *(float2*)&out[base + 8*HW] = make_float2(acc[m][nt][2], acc[m][nt][3]);
        }
}

// ---------------- attention GEMM (fp32) ----------------
__global__ __launch_bounds__(256)
void attn_gemm_kernel(const float* __restrict__ q, const float* __restrict__ k,
                      float* __restrict__ attn)
{
    const int p = blockIdx.x;        // 0..8
    const int b = blockIdx.y;        // 0..7
    const int i = p/3, j = p - 3*(p/3);
    const int tid = threadIdx.y*16 + threadIdx.x;

    __shared__ float Qs[16][96];
    __shared__ float Ks[16][96];

    float acc[6][6];
    #pragma unroll
    for (int r=0;r<6;r++)
        #pragma unroll
        for (int s=0;s<6;s++) acc[r][s]=0.f;

    for (int l0 = 0; l0 < 1024; l0 += 16) {
        #pragma unroll
        for (int it = 0; it < 6; it++) {
            int e = tid + it*256;
            int kk = e/96, c = e - kk*96;
            int l = l0 + kk;
            int gh = 3*(l>>5) + i, gw = 3*(l&31) + j;
            size_t off = ((size_t)(b*CCH + c)*HH + gh)*WW + gw;
            Qs[kk][c] = q[off];
            Ks[kk][c] = k[off];
        }
        __syncthreads();
        #pragma unroll
        for (int kk=0; kk<16; kk++) {
            float rq[6], rk[6];
            #pragma unroll
            for (int r=0;r<6;r++) {
                rq[r] = Qs[kk][threadIdx.y*6 + r];
                rk[r] = Ks[kk][threadIdx.x*6 + r];
            }
            #pragma unroll
            for (int r=0;r<6;r++)
                #pragma unroll
                for (int s=0;s<6;s++)
                    acc[r][s] = fmaf(rq[r], rk[s], acc[r][s]);
        }
        __syncthreads();
    }
    #pragma unroll
    for (int r=0;r<6;r++)
        #pragma unroll
        for (int s=0;s<6;s++) {
            int cq = threadIdx.y*6 + r, ck = threadIdx.x*6 + s;
            attn[((size_t)(b*CCH + ck)*CCH + cq)*9 + p] = acc[r][s];
        }
}

// ---------------- softmax over 864 per (b, ck) row ----------------
__global__ __launch_bounds__(256)
void softmax_kernel(float* __restrict__ attn)
{
    float* row = attn + (size_t)blockIdx.x * 864;
    const float scale = 0.034020690871988585f;   // 1/sqrt(864)
    const int tid = threadIdx.x;
    __shared__ float red[256];

    float v[4];
    float mx = -1e30f;
    #pragma unroll
    for (int it=0; it<4; it++) {
        int idx = tid + it*256;
        v[it] = (idx < 864) ? row[idx]*scale : -1e30f;
        mx = fmaxf(mx, v[it]);
    }
    red[tid] = mx; __syncthreads();
    for (int s=128; s>0; s>>=1) { if (tid<s) red[tid]=fmaxf(red[tid],red[tid+s]); __syncthreads(); }
    mx = red[0]; __syncthreads();

    float sum = 0.f;
    #pragma unroll
    for (int it=0; it<4; it++) {
        int idx = tid + it*256;
        v[it] = (idx < 864) ? expf(v[it]-mx) : 0.f;
        sum += v[it];
    }
    red[tid] = sum; __syncthreads();
    for (int s=128; s>0; s>>=1) { if (tid<s) red[tid]+=red[tid+s]; __syncthreads(); }
    float inv = 1.f/red[0];

    #pragma unroll
    for (int it=0; it<4; it++) {
        int idx = tid + it*256;
        if (idx < 864) row[idx] = v[it]*inv;
    }
}

// ---------------- batchnorm statistics (biased var) ----------------
__global__ __launch_bounds__(256)
void bnstats_kernel(const float* __restrict__ y1, const float* __restrict__ y2,
                    const float* __restrict__ y3,
                    float* __restrict__ meanv, float* __restrict__ istdv)
{
    const int t = blockIdx.x / CCH, c = blockIdx.x - t*CCH;
    const float* src = (t==0) ? y1 : (t==1) ? y2 : y3;
    float s = 0.f, sq = 0.f;
    for (int e = threadIdx.x; e < BATCH*HW; e += 256) {
        int b = e / HW, hw = e - b*HW;
        float vv = src[((size_t)b*CCH + c)*HW + hw];
        s += vv; sq = fmaf(vv, vv, sq);
    }
    __shared__ float sh1[256], sh2[256];
    sh1[threadIdx.x]=s; sh2[threadIdx.x]=sq;
    __syncthreads();
    for (int st=128; st>0; st>>=1) {
        if (threadIdx.x < st) { sh1[threadIdx.x]+=sh1[threadIdx.x+st]; sh2[threadIdx.x]+=sh2[threadIdx.x+st]; }
        __syncthreads();
    }
    if (threadIdx.x==0) {
        const float invN = 1.f / (float)(BATCH*HW);
        float m = sh1[0]*invN;
        float var = sh2[0]*invN - m*m;
        meanv[blockIdx.x] = m;
        istdv[blockIdx.x] = rsqrtf(var + 1e-5f);
    }
}

// ---------------- final fuse: out = (x+y, x) ----------------
__global__ __launch_bounds__(256)
void finalize_kernel(const float* __restrict__ x1, const float* __restrict__ x2,
                     const float* __restrict__ y1, const float* __restrict__ y2,
                     const float* __restrict__ y3,
                     const float* __restrict__ meanv, const float* __restrict__ istdv,
                     float* __restrict__ out, int writeSecond)
{
    int idx = blockIdx.x*256 + threadIdx.x;
    if (idx >= N1OUT) return;
    int hw = idx % HW;
    int c  = (idx / HW) % (2*CCH);
    int b  = idx / (HW*2*CCH);
    float xv, yv;
    if (c < CCH) {
        size_t off = ((size_t)b*CCH + c)*HW + hw;
        xv = x1[off];
        float a = (y1[off]-meanv[c])       * istdv[c];
        float g = (y2[off]-meanv[CCH+c])   * istdv[CCH+c];
        yv = a*g;
    } else {
        int cc = c - CCH;
        size_t off = ((size_t)b*CCH + cc)*HW + hw;
        xv = x2[off];
        yv = (y3[off]-meanv[2*CCH+cc]) * istdv[2*CCH+cc];
    }
    out[idx] = xv + yv;
    if (writeSecond) out[N1OUT + idx] = xv;
}

// ---------------- launch ----------------
extern "C" void kernel_launch(void* const* d_in, const int* in_sizes, int n_in,
                              void* d_out, int out_size)
{
    const float* x1  = (const float*)d_in[0];
    const float* x2  = (const float*)d_in[1];
    const float* w1  = (const float*)d_in[2];
    const float* w2  = (const float*)d_in[3];
    const float* wa1 = (const float*)d_in[4];
    const float* wa2 = (const float*)d_in[5];
    const float* wa3 = (const float*)d_in[6];
    float* out = (float*)d_out;

    float *y1,*y2,*q,*k,*v,*y3,*attn,*meanv,*istdv;
    unsigned *x1h,*x2h,*vh,*w1h,*w2h,*wa1h,*wa2h,*wa3h,*wath;
    cudaGetSymbolAddress((void**)&y1,   g_y1);
    cudaGetSymbolAddress((void**)&y2,   g_y2);
    cudaGetSymbolAddress((void**)&q,    g_q);
    cudaGetSymbolAddress((void**)&k,    g_k);
    cudaGetSymbolAddress((void**)&v,    g_v);
    cudaGetSymbolAddress((void**)&y3,   g_y3);
    cudaGetSymbolAddress((void**)&attn, g_attn);
    cudaGetSymbolAddress((void**)&meanv,g_mean);
    cudaGetSymbolAddress((void**)&istdv,g_istd);
    cudaGetSymbolAddress((void**)&x1h,  g_x1h);
    cudaGetSymbolAddress((void**)&x2h,  g_x2h);
    cudaGetSymbolAddress((void**)&vh,   g_vh);
    cudaGetSymbolAddress((void**)&w1h,  g_w1h);
    cudaGetSymbolAddress((void**)&w2h,  g_w2h);
    cudaGetSymbolAddress((void**)&wa1h, g_wa1h);
    cudaGetSymbolAddress((void**)&wa2h, g_wa2h);
    cudaGetSymbolAddress((void**)&wa3h, g_wa3h);
    cudaGetSymbolAddress((void**)&wath, g_wath);

    static int smem_set = 0;
    const int CONV_SMEM = (2*WCH2 + 2*PBUF) * 4;   // 68096 B
    if (!smem_set) {
        cudaFuncSetAttribute(conv3x3_fp16_kernel,
                             cudaFuncAttributeMaxDynamicSharedMemorySize, CONV_SMEM);
        smem_set = 1;
    }

    // 1. inputs -> interleaved half2 (one launch, two streams)
    cvt_pair_kernel<<<dim3((NPIX2+255)/256, 2), 256>>>(x1, x1h, x2, x2h);

    // 2. all fixed weights -> fp16 fragment layout (one launch)
    wprep_all_kernel<<<dim3((12*WCH2+255)/256, 5), 256>>>(
        w1, w2, wa1, wa2, wa3, w1h, w2h, wa1h, wa2h, wa3h);

    dim3 tcgrid(72, 1, 8);   // 12 row-tiles x 6 col-tiles, 8 batches

    // 3. convs (fp16 tensor cores, 6-warp low-traffic tiling)
    conv3x3_fp16_kernel<<<tcgrid, 192, CONV_SMEM>>>(x1h, x1h, 48, 48, w1h,  0, y1);
    conv3x3_fp16_kernel<<<tcgrid, 192, CONV_SMEM>>>(x2h, x2h, 48, 48, w2h,  0, y2);
    conv3x3_fp16_kernel<<<tcgrid, 192, CONV_SMEM>>>(x1h, x2h, 48, 96, wa1h, 0, q);
    conv3x3_fp16_kernel<<<tcgrid, 192, CONV_SMEM>>>(x1h, x2h, 48, 96, wa2h, 0, k);
    conv3x3_fp16_kernel<<<tcgrid, 192, CONV_SMEM>>>(x1h, x2h, 48, 96, wa3h, 0, v);

    // 4. attention weights
    dim3 cblk(16,16);
    attn_gemm_kernel<<<dim3(9,8), cblk>>>(q, k, attn);
    softmax_kernel<<<BATCH*CCH, 256>>>(attn);

    // 5. v -> half2 ; attn weights -> fp16 fragment layout (per batch)
    cvt_pair_kernel<<<dim3((NPIX2+255)/256, 1), 256>>>(v, vh, v, vh);
    wprep_attn_kernel<<<dim3((6*WCH2+255)/256, 1, BATCH), 256>>>(attn, wath);

    // 6. attn @ v_unf == per-batch 3x3 conv
    conv3x3_fp16_kernel<<<tcgrid, 192, CONV_SMEM>>>(vh, vh, 48, 48, wath, 6L*WCH2, y3);

    // 7. batchnorm stats + fused epilogue
    bnstats_kernel<<<3*CCH, 256>>>(y1, y2, y3, meanv, istdv);
    int writeSecond = (out_size >= 2*N1OUT) ? 1 : 0;
    finalize_kernel<<<(N1OUT + 255)/256, 256>>>(x1, x2, y1, y2, y3, meanv, istdv, out, writeSecond);
}

// round 10
// speedup vs baseline: 2.1092x; 1.4453x over previous
#include <cuda_runtime.h>
#include <cuda_fp16.h>
#include <math.h>

#define BATCH 8
#define CCH 96
#define HH 96
#define WW 96
#define HW (HH*WW)                 // 9216
#define NPIX 7077888               // 8*96*96*96
#define NPIX2 (NPIX/2)
#define N1OUT 14155776             // 8*192*96*96

// weight layout: [chunk16ci][tap(9)][cotile(6)][lane(32)][4 frag words(half2)]
#define WCH2  6912                 // words per 16-ci chunk = 9*6*32*4
// patch smem: [ci2&3][row(10)][colpair] word=half2(2ci2,2ci2+1); pair (ci2, ci2+4) adjacent
#define PRS2  40
#define PCIS  400
#define PBUF  1600

// ---------------- scratch (static __device__, no allocation) ----------------
__device__ float g_y1[NPIX];
__device__ float g_y2[NPIX];
__device__ float g_q [NPIX];
__device__ float g_k [NPIX];
__device__ float g_y3[NPIX];
__device__ float g_attn4[4*BATCH*CCH*CCH*9];   // split-K partials
__device__ float g_mean[3*CCH];
__device__ float g_istd[3*CCH];

// ci-pair-interleaved half2 inputs
__device__ __align__(16) unsigned g_x1h[NPIX2];
__device__ __align__(16) unsigned g_x2h[NPIX2];
__device__ __align__(16) unsigned g_vh [NPIX2];
// fragment-order fp16 weights
__device__ __align__(16) unsigned g_w1h [6*WCH2];
__device__ __align__(16) unsigned g_w2h [6*WCH2];
__device__ __align__(16) unsigned g_wa1h[12*WCH2];
__device__ __align__(16) unsigned g_wa2h[12*WCH2];
__device__ __align__(16) unsigned g_wa3h[12*WCH2];
__device__ __align__(16) unsigned g_wath[BATCH*6*WCH2];

struct ConvJob {
    const unsigned* inA;
    const unsigned* inB;
    const unsigned* wh;
    long  wstride;
    float* outf;
    unsigned* outh;
    int outmode;
};
struct ConvJobs {
    ConvJob j[3];
    int csplit2, cin2;
};

__device__ __forceinline__ unsigned packh2(float a, float b) {
    __half2 h = __floats2half2_rn(a, b);
    return *(unsigned*)&h;
}

// ---------------- fp32 -> ci-pair-interleaved half2 ----------------
__global__ __launch_bounds__(256)
void cvt_pair_kernel(const float* __restrict__ s1, unsigned* __restrict__ d1,
                     const float* __restrict__ s2, unsigned* __restrict__ d2)
{
    const float* src = blockIdx.y ? s2 : s1;
    unsigned* dst    = blockIdx.y ? d2 : d1;
    int e = blockIdx.x*256 + threadIdx.x;
    if (e >= NPIX2) return;
    int b = e / (48*HW), r = e - b*48*HW;
    int ci2 = r / HW, hw = r - ci2*HW;
    size_t off = ((size_t)b*CCH + 2*ci2)*HW + hw;
    dst[e] = packh2(src[off], src[off + HW]);
}

// ---------------- weight pre-transform (m16n8k16 fragment order) -----------
__global__ __launch_bounds__(256)
void wprep_all_kernel(const float* __restrict__ w1, const float* __restrict__ w2,
                      const float* __restrict__ wa1, const float* __restrict__ wa2,
                      const float* __restrict__ wa3,
                      unsigned* __restrict__ d1, unsigned* __restrict__ d2,
                      unsigned* __restrict__ d3, unsigned* __restrict__ d4,
                      unsigned* __restrict__ d5)
{
    const int id = blockIdx.y;
    const float* src; unsigned* dst; int cin;
    if      (id == 0) { src = w1;  dst = d1; cin = 96;  }
    else if (id == 1) { src = w2;  dst = d2; cin = 96;  }
    else if (id == 2) { src = wa1; dst = d3; cin = 192; }
    else if (id == 3) { src = wa2; dst = d4; cin = 192; }
    else              { src = wa3; dst = d5; cin = 192; }
    const int nwords = (cin >> 4) * WCH2;
    int e = blockIdx.x*256 + threadIdx.x;
    if (e >= nwords) return;
    int chunk = e / WCH2, rm = e - chunk*WCH2;
    int w = rm & 3, lane = (rm >> 2) & 31, mtap = rm >> 7;
    int tap = mtap / 6, mt = mtap - 6*tap;
    int g = lane >> 2, t = lane & 3;
    int co = mt*16 + g + (w & 1)*8;
    int ci = chunk*16 + 2*t + ((w >> 1) & 1)*8;
    dst[e] = packh2(src[((size_t)co*cin + ci)*9 + tap],
                    src[((size_t)co*cin + ci + 1)*9 + tap]);
}

// ---------------- tensor-core 3x3 conv, fp16 m16n8k16, multi-job -----------
// block: 192 thr (6 warps); tile 96co x 128px; blockIdx.y selects job.
__global__ __launch_bounds__(192, 2)
void conv3x3_fp16_kernel(ConvJobs jobs)
{
    extern __shared__ unsigned dsm[];
    const ConvJob J = jobs.j[blockIdx.y];
    const unsigned* __restrict__ inAh = J.inA;
    const unsigned* __restrict__ inBh = J.inB;
    const int csplit2 = jobs.csplit2, cin2 = jobs.cin2;

    const int tid  = threadIdx.x;
    const int lane = tid & 31, wid = tid >> 5;
    const int g = lane >> 2, t = lane & 3;
    const int cog = wid >> 1;
    const int rp  = wid & 1;
    const int b   = blockIdx.z;
    const int byk = blockIdx.x / 6, bxk = blockIdx.x - 6*byk;
    const int by0 = byk*8, bx0 = bxk*16;

    const unsigned smem_b = (unsigned)__cvta_generic_to_shared(dsm);
    unsigned* psmem = dsm + 2*WCH2;

    int pgoff[8], psoff[8], pci[8];
    bool lok[8], sok[8];
    #pragma unroll
    for (int it = 0; it < 8; it++) {
        int e = tid + it*192;
        int ci = e / 180, r2 = e - ci*180;
        int row = r2 / 18, col = r2 - row*18;
        int gh = by0 + row - 1, gw = bx0 + col - 1;
        bool inp = (e < 1440);
        bool ok = inp && gh >= 0 && gh < HH && gw >= 0 && gw < WW;
        lok[it] = ok; sok[it] = inp;
        pgoff[it] = ok ? gh*WW + gw : 0;
        psoff[it] = inp ? (ci & 3)*PCIS + row*PRS2 + col*2 + (ci >> 2) : 0;
        pci[it]   = ci;
    }

    const unsigned* wsrc0 = J.wh + (size_t)J.wstride*b;

    #pragma unroll
    for (int k2 = 0; k2 < 9; k2++) {
        int idx = tid + k2*192;
        asm volatile("cp.async.cg.shared.global [%0], [%1], 16;"
                     :: "r"(smem_b + idx*16), "l"(wsrc0 + idx*4) : "memory");
    }
    asm volatile("cp.async.commit_group;" ::: "memory");
    {
        unsigned pv[8];
        #pragma unroll
        for (int it = 0; it < 8; it++) {
            int gci = pci[it];
            const unsigned* src = (gci < csplit2)
                ? inAh + ((size_t)b*csplit2 + gci)*HW
                : inBh + ((size_t)b*(cin2-csplit2) + (gci-csplit2))*HW;
            pv[it] = lok[it] ? src[pgoff[it]] : 0u;
        }
        #pragma unroll
        for (int it = 0; it < 8; it++)
            if (sok[it]) psmem[psoff[it]] = pv[it];
    }
    asm volatile("cp.async.wait_group 0;" ::: "memory");
    __syncthreads();

    float acc[2][8][4];
    #pragma unroll
    for (int m=0;m<2;m++)
        #pragma unroll
        for (int nt=0;nt<8;nt++)
            #pragma unroll
            for (int r=0;r<4;r++) acc[m][nt][r] = 0.f;

    const int nchunk = cin2 >> 3;
    for (int ch = 0; ch < nchunk; ch++) {
        const int cur = ch & 1;
        const bool more = (ch + 1 < nchunk);

        unsigned pv[8];
        if (more) {
            const unsigned* wsrc = wsrc0 + (size_t)(ch+1)*WCH2;
            const unsigned wdst = smem_b + (cur^1)*WCH2*4;
            #pragma unroll
            for (int k2 = 0; k2 < 9; k2++) {
                int idx = tid + k2*192;
                asm volatile("cp.async.cg.shared.global [%0], [%1], 16;"
                             :: "r"(wdst + idx*16), "l"(wsrc + idx*4) : "memory");
            }
            asm volatile("cp.async.commit_group;" ::: "memory");
            const int ci0 = (ch+1) << 3;
            #pragma unroll
            for (int it = 0; it < 8; it++) {
                int gci = ci0 + pci[it];
                const unsigned* src = (gci < csplit2)
                    ? inAh + ((size_t)b*csplit2 + gci)*HW
                    : inBh + ((size_t)b*(cin2-csplit2) + (gci-csplit2))*HW;
                pv[it] = lok[it] ? src[pgoff[it]] : 0u;
            }
        }

        const unsigned wbase = smem_b + cur*WCH2*4;
        const unsigned pbase = smem_b + (2*WCH2 + cur*PBUF)*4;
        #pragma unroll
        for (int tap = 0; tap < 9; tap++) {
            const int i = tap/3, j = tap - 3*(tap/3);
            unsigned a[2][4];
            #pragma unroll
            for (int m = 0; m < 2; m++) {
                const int mt = cog*2 + m;
                asm volatile("ld.shared.v4.b32 {%0,%1,%2,%3}, [%4];"
                    : "=r"(a[m][0]), "=r"(a[m][1]), "=r"(a[m][2]), "=r"(a[m][3])
                    : "r"(wbase + (((tap*6 + mt)*32 + lane)*16)));
            }
            #pragma unroll
            for (int nt = 0; nt < 8; nt++) {
                const int py = 4*rp + (nt & 3);
                const int cb2 = (nt >> 2) * 8;
                unsigned b0, b1;
                asm volatile("ld.shared.v2.b32 {%0,%1}, [%2];"
                    : "=r"(b0), "=r"(b1)
                    : "r"(pbase + (t*PCIS + (py+i)*PRS2 + (cb2+j+g)*2)*4));
                #pragma unroll
                for (int m = 0; m < 2; m++) {
                    asm volatile(
                        "mma.sync.aligned.m16n8k16.row.col.f32.f16.f16.f32 "
                        "{%0,%1,%2,%3}, {%4,%5,%6,%7}, {%8,%9}, {%0,%1,%2,%3};"
                        : "+f"(acc[m][nt][0]), "+f"(acc[m][nt][1]),
                          "+f"(acc[m][nt][2]), "+f"(acc[m][nt][3])
                        : "r"(a[m][0]), "r"(a[m][1]), "r"(a[m][2]), "r"(a[m][3]),
                          "r"(b0), "r"(b1));
                }
            }
        }

        if (more) {
            unsigned* pd = psmem + (cur^1)*PBUF;
            #pragma unroll
            for (int it = 0; it < 8; it++)
                if (sok[it]) pd[psoff[it]] = pv[it];
            asm volatile("cp.async.wait_group 0;" ::: "memory");
        }
        __syncthreads();
    }

    // ---- writeback ----
    if (J.outmode == 0) {
        float* out = J.outf;
        #pragma unroll
        for (int m = 0; m < 2; m++)
            #pragma unroll
            for (int nt = 0; nt < 8; nt++) {
                int co  = cog*32 + m*16 + g;
                int row = by0 + 4*rp + (nt & 3);
                int col = bx0 + (nt >> 2)*8 + 2*t;
                size_t base = (((size_t)b*CCH + co)*HH + row)*WW + col;
                *(float2*)&out[base]        = make_float2(acc[m][nt][0], acc[m][nt][1]);
                *(float2*)&out[base + 8*HW] = make_float2(acc[m][nt][2], acc[m][nt][3]);
            }
    } else {
        // interleaved half2 output: pair adjacent co via shfl_xor(4)
        unsigned* outh = J.outh;
        #pragma unroll
        for (int m = 0; m < 2; m++)
            #pragma unroll
            for (int nt = 0; nt < 8; nt++) {
                float a0 = acc[m][nt][0], a1 = acc[m][nt][1];
                float a2 = acc[m][nt][2], a3 = acc[m][nt][3];
                float p0 = __shfl_xor_sync(0xFFFFFFFFu, a0, 4);
                float p1 = __shfl_xor_sync(0xFFFFFFFFu, a1, 4);
                float p2 = __shfl_xor_sync(0xFFFFFFFFu, a2, 4);
                float p3 = __shfl_xor_sync(0xFFFFFFFFu, a3, 4);
                int row = by0 + 4*rp + (nt & 3);
                int col = bx0 + (nt >> 2)*8 + 2*t;
                int B = cog*32 + m*16;
                int ci2; unsigned w0, w1;
                if ((g & 1) == 0) {
                    ci2 = (B >> 1) + (g >> 1);
                    w0 = packh2(a0, p0); w1 = packh2(a1, p1);
                } else {
                    ci2 = (B >> 1) + 4 + ((g - 1) >> 1);
                    w0 = packh2(p2, a2); w1 = packh2(p3, a3);
                }
                *(uint2*)&outh[((size_t)b*48 + ci2)*HW + row*WW + col] =
                    make_uint2(w0, w1);
            }
    }
}

// ---------------- attention GEMM, split-K over lattice ----------------
// grid (9, 8, 4): p, b, ks. Each block: 96x96 over 256 l-values.
__global__ __launch_bounds__(256)
void attn_split_kernel(const float* __restrict__ q, const float* __restrict__ k,
                       float* __restrict__ attn4)
{
    const int p = blockIdx.x;
    const int b = blockIdx.y;
    const int ks = blockIdx.z;
    const int i = p/3, j = p - 3*(p/3);
    const int tid = threadIdx.y*16 + threadIdx.x;

    __shared__ float Qs[16][102];
    __shared__ float Ks[16][102];

    float acc[6][6];
    #pragma unroll
    for (int r=0;r<6;r++)
        #pragma unroll
        for (int s=0;s<6;s++) acc[r][s]=0.f;

    const int lbase = ks*256;
    for (int l0 = lbase; l0 < lbase + 256; l0 += 16) {
        #pragma unroll
        for (int it = 0; it < 6; it++) {
            int e = tid + it*256;
            int kk = e & 15, c = e >> 4;    // kk fastest -> coalesced-ish
            int l = l0 + kk;
            int gh = 3*(l>>5) + i, gw = 3*(l&31) + j;
            size_t off = ((size_t)(b*CCH + c)*HH + gh)*WW + gw;
            Qs[kk][c] = q[off];
            Ks[kk][c] = k[off];
        }
        __syncthreads();
        #pragma unroll
        for (int kk=0; kk<16; kk++) {
            float rq[6], rk[6];
            #pragma unroll
            for (int r=0;r<6;r++) {
                rq[r] = Qs[kk][threadIdx.y*6 + r];
                rk[r] = Ks[kk][threadIdx.x*6 + r];
            }
            #pragma unroll
            for (int r=0;r<6;r++)
                #pragma unroll
                for (int s=0;s<6;s++)
                    acc[r][s] = fmaf(rq[r], rk[s], acc[r][s]);
        }
        __syncthreads();
    }
    #pragma unroll
    for (int r=0;r<6;r++)
        #pragma unroll
        for (int s=0;s<6;s++) {
            int cq = threadIdx.y*6 + r, ck = threadIdx.x*6 + s;
            attn4[((size_t)(ks*768 + b*CCH + ck))*864 + cq*9 + p] = acc[r][s];
        }
}

// ---------------- softmax + direct fragment-layout weight emit -------------
// block = one (b, ck) row; sums 4 split-K partials, softmaxes 864,
// writes y3-conv weights straight into g_wath fragment order.
__global__ __launch_bounds__(256)
void softmax_kernel(const float* __restrict__ attn4, unsigned* __restrict__ wath)
{
    const int rowid = blockIdx.x;          // b*96 + ck
    const float scale = 0.034020690871988585f;   // 1/sqrt(864)
    const int tid = threadIdx.x;
    __shared__ float red[256];
    __shared__ float sm[864];

    float v[4];
    float mx = -1e30f;
    #pragma unroll
    for (int it=0; it<4; it++) {
        int idx = tid + it*256;
        float s = -1e30f;
        if (idx < 864) {
            s = attn4[((size_t)(0*768 + rowid))*864 + idx]
              + attn4[((size_t)(1*768 + rowid))*864 + idx]
              + attn4[((size_t)(2*768 + rowid))*864 + idx]
              + attn4[((size_t)(3*768 + rowid))*864 + idx];
            s *= scale;
        }
        v[it] = s;
        mx = fmaxf(mx, s);
    }
    red[tid] = mx; __syncthreads();
    for (int s=128; s>0; s>>=1) { if (tid<s) red[tid]=fmaxf(red[tid],red[tid+s]); __syncthreads(); }
    mx = red[0]; __syncthreads();

    float sum = 0.f;
    #pragma unroll
    for (int it=0; it<4; it++) {
        int idx = tid + it*256;
        v[it] = (idx < 864) ? expf(v[it]-mx) : 0.f;
        sum += v[it];
    }
    red[tid] = sum; __syncthreads();
    for (int s=128; s>0; s>>=1) { if (tid<s) red[tid]+=red[tid+s]; __syncthreads(); }
    float inv = 1.f/red[0];
    __syncthreads();

    #pragma unroll
    for (int it=0; it<4; it++) {
        int idx = tid + it*256;
        if (idx < 864) sm[idx] = v[it]*inv;
    }
    __syncthreads();

    // emit fragment-layout half2 words for output channel co=ck
    const int bb = rowid / CCH, ck = rowid - (rowid/CCH)*CCH;
    const int mt = ck >> 4, gq = ck & 7, hiw = (ck >> 3) & 1;
    #pragma unroll
    for (int it = 0; it < 2; it++) {
        int e = tid + it*256;
        if (e < 432) {
            int u = e / 9, tap = e - 9*u;      // u = cq pair index
            int chunk = u >> 3, hi2 = (u & 7) >> 2, t = u & 3;
            int w = hiw | (hi2 << 1);
            int lane = (gq << 2) | t;
            wath[(size_t)bb*6*WCH2 + chunk*WCH2 + ((tap*6 + mt)*32 + lane)*4 + w] =
                packh2(sm[2*u*9 + tap], sm[(2*u + 1)*9 + tap]);
        }
    }
}

// ---------------- batchnorm statistics (biased var) ----------------
__global__ __launch_bounds__(256)
void bnstats_kernel(const float* __restrict__ y1, const float* __restrict__ y2,
                    const float* __restrict__ y3,
                    float* __restrict__ meanv, float* __restrict__ istdv)
{
    const int t = blockIdx.x / CCH, c = blockIdx.x - t*CCH;
    const float* src = (t==0) ? y1 : (t==1) ? y2 : y3;
    float s = 0.f, sq = 0.f;
    for (int e = threadIdx.x; e < BATCH*HW; e += 256) {
        int b = e / HW, hw = e - b*HW;
        float vv = src[((size_t)b*CCH + c)*HW + hw];
        s += vv; sq = fmaf(vv, vv, sq);
    }
    __shared__ float sh1[256], sh2[256];
    sh1[threadIdx.x]=s; sh2[threadIdx.x]=sq;
    __syncthreads();
    for (int st=128; st>0; st>>=1) {
        if (threadIdx.x < st) { sh1[threadIdx.x]+=sh1[threadIdx.x+st]; sh2[threadIdx.x]+=sh2[threadIdx.x+st]; }
        __syncthreads();
    }
    if (threadIdx.x==0) {
        const float invN = 1.f / (float)(BATCH*HW);
        float m = sh1[0]*invN;
        float var = sh2[0]*invN - m*m;
        meanv[blockIdx.x] = m;
        istdv[blockIdx.x] = rsqrtf(var + 1e-5f);
    }
}

// ---------------- final fuse: out = (x+y, x) ----------------
__global__ __launch_bounds__(256)
void finalize_kernel(const float* __restrict__ x1, const float* __restrict__ x2,
                     const float* __restrict__ y1, const float* __restrict__ y2,
                     const float* __restrict__ y3,
                     const float* __restrict__ meanv, const float* __restrict__ istdv,
                     float* __restrict__ out, int writeSecond)
{
    int idx = blockIdx.x*256 + threadIdx.x;
    if (idx >= N1OUT) return;
    int hw = idx % HW;
    int c  = (idx / HW) % (2*CCH);
    int b  = idx / (HW*2*CCH);
    float xv, yv;
    if (c < CCH) {
        size_t off = ((size_t)b*CCH + c)*HW + hw;
        xv = x1[off];
        float a = (y1[off]-meanv[c])       * istdv[c];
        float g = (y2[off]-meanv[CCH+c])   * istdv[CCH+c];
        yv = a*g;
    } else {
        int cc = c - CCH;
        size_t off = ((size_t)b*CCH + cc)*HW + hw;
        xv = x2[off];
        yv = (y3[off]-meanv[2*CCH+cc]) * istdv[2*CCH+cc];
    }
    out[idx] = xv + yv;
    if (writeSecond) out[N1OUT + idx] = xv;
}

// ---------------- launch ----------------
extern "C" void kernel_launch(void* const* d_in, const int* in_sizes, int n_in,
                              void* d_out, int out_size)
{
    const float* x1  = (const float*)d_in[0];
    const float* x2  = (const float*)d_in[1];
    const float* w1  = (const float*)d_in[2];
    const float* w2  = (const float*)d_in[3];
    const float* wa1 = (const float*)d_in[4];
    const float* wa2 = (const float*)d_in[5];
    const float* wa3 = (const float*)d_in[6];
    float* out = (float*)d_out;

    float *y1,*y2,*q,*k,*y3,*attn4,*meanv,*istdv;
    unsigned *x1h,*x2h,*vh,*w1h,*w2h,*wa1h,*wa2h,*wa3h,*wath;
    cudaGetSymbolAddress((void**)&y1,   g_y1);
    cudaGetSymbolAddress((void**)&y2,   g_y2);
    cudaGetSymbolAddress((void**)&q,    g_q);
    cudaGetSymbolAddress((void**)&k,    g_k);
    cudaGetSymbolAddress((void**)&y3,   g_y3);
    cudaGetSymbolAddress((void**)&attn4,g_attn4);
    cudaGetSymbolAddress((void**)&meanv,g_mean);
    cudaGetSymbolAddress((void**)&istdv,g_istd);
    cudaGetSymbolAddress((void**)&x1h,  g_x1h);
    cudaGetSymbolAddress((void**)&x2h,  g_x2h);
    cudaGetSymbolAddress((void**)&vh,   g_vh);
    cudaGetSymbolAddress((void**)&w1h,  g_w1h);
    cudaGetSymbolAddress((void**)&w2h,  g_w2h);
    cudaGetSymbolAddress((void**)&wa1h, g_wa1h);
    cudaGetSymbolAddress((void**)&wa2h, g_wa2h);
    cudaGetSymbolAddress((void**)&wa3h, g_wa3h);
    cudaGetSymbolAddress((void**)&wath, g_wath);

    static int smem_set = 0;
    const int CONV_SMEM = (2*WCH2 + 2*PBUF) * 4;   // 68096 B
    if (!smem_set) {
        cudaFuncSetAttribute(conv3x3_fp16_kernel,
                             cudaFuncAttributeMaxDynamicSharedMemorySize, CONV_SMEM);
        smem_set = 1;
    }

    // 1. inputs -> interleaved half2
    cvt_pair_kernel<<<dim3((NPIX2+255)/256, 2), 256>>>(x1, x1h, x2, x2h);

    // 2. all fixed weights -> fp16 fragment layout
    wprep_all_kernel<<<dim3((12*WCH2+255)/256, 5), 256>>>(
        w1, w2, wa1, wa2, wa3, w1h, w2h, wa1h, wa2h, wa3h);

    // 3. convs y1 + y2 (merged launch)
    {
        ConvJobs jb{};
        jb.csplit2 = 48; jb.cin2 = 48;
        jb.j[0] = { x1h, x1h, w1h, 0, y1, 0, 0 };
        jb.j[1] = { x2h, x2h, w2h, 0, y2, 0, 0 };
        conv3x3_fp16_kernel<<<dim3(72, 2, 8), 192, CONV_SMEM>>>(jb);
    }
    // 4. convs q + k + v (merged; v emits half2 directly)
    {
        ConvJobs jb{};
        jb.csplit2 = 48; jb.cin2 = 96;
        jb.j[0] = { x1h, x2h, wa1h, 0, q, 0, 0 };
        jb.j[1] = { x1h, x2h, wa2h, 0, k, 0, 0 };
        jb.j[2] = { x1h, x2h, wa3h, 0, 0, vh, 1 };
        conv3x3_fp16_kernel<<<dim3(72, 3, 8), 192, CONV_SMEM>>>(jb);
    }

    // 5. attention logits (split-K x4) + softmax emitting conv weights
    attn_split_kernel<<<dim3(9, 8, 4), dim3(16,16)>>>(q, k, attn4);
    softmax_kernel<<<BATCH*CCH, 256>>>(attn4, wath);

    // 6. attn @ v_unf == per-batch 3x3 conv
    {
        ConvJobs jb{};
        jb.csplit2 = 48; jb.cin2 = 48;
        jb.j[0] = { vh, vh, wath, 6L*WCH2, y3, 0, 0 };
        conv3x3_fp16_kernel<<<dim3(72, 1, 8), 192, CONV_SMEM>>>(jb);
    }

    // 7. batchnorm stats + fused epilogue
    bnstats_kernel<<<3*CCH, 256>>>(y1, y2, y3, meanv, istdv);
    int writeSecond = (out_size >= 2*N1OUT) ? 1 : 0;
    finalize_kernel<<<(N1OUT + 255)/256, 256>>>(x1, x2, y1, y2, y3, meanv, istdv, out, writeSecond);
}